// round 7
// baseline (speedup 1.0000x reference)
#include <cuda_runtime.h>
#include <math_constants.h>

#define SEQ    2048
#define DM     1024
#define NH     16
#define DH     64
#define BH     64
#define MR     8192
#define KDIM   1024

__device__ float g_q[(size_t)BH*SEQ*DH];
__device__ float g_k[(size_t)BH*SEQ*DH];
__device__ float g_v[(size_t)BH*SEQ*DH];
__device__ float g_attn[(size_t)MR*DM];
__device__ float g_x[(size_t)MR*DM];
__device__ float g_wqkv[(size_t)DM*3*DM];
__device__ float g_wout[(size_t)DM*DM];

__device__ __forceinline__ unsigned cvt_tf32(float f){
    unsigned u; asm("cvt.rna.tf32.f32 %0, %1;" : "=r"(u) : "f"(f)); return u;
}
__device__ __forceinline__ float tf32f(float f){ return __uint_as_float(cvt_tf32(f)); }

__device__ __forceinline__ void mma8(float4& d, unsigned a0, unsigned a1, unsigned a2,
                                     unsigned a3, unsigned b0, unsigned b1){
    asm volatile(
      "mma.sync.aligned.m16n8k8.row.col.f32.tf32.tf32.f32 "
      "{%0,%1,%2,%3},{%4,%5,%6,%7},{%8,%9},{%0,%1,%2,%3};"
      : "+f"(d.x), "+f"(d.y), "+f"(d.z), "+f"(d.w)
      : "r"(a0), "r"(a1), "r"(a2), "r"(a3), "r"(b0), "r"(b1));
}
__device__ __forceinline__ void ldsm4(unsigned* r, unsigned addr){
    asm volatile("ldmatrix.sync.aligned.m8n8.x4.shared.b16 {%0,%1,%2,%3}, [%4];"
        : "=r"(r[0]), "=r"(r[1]), "=r"(r[2]), "=r"(r[3]) : "r"(addr));
}
__device__ __forceinline__ void cpasync16(void* smem, const void* g){
    unsigned s = (unsigned)__cvta_generic_to_shared(smem);
    asm volatile("cp.async.cg.shared.global [%0], [%1], 16;" :: "r"(s), "l"(g));
}
__device__ __forceinline__ void cp_commit(){ asm volatile("cp.async.commit_group;"); }
template<int N> __device__ __forceinline__ void cp_wait(){
    asm volatile("cp.async.wait_group %0;" :: "n"(N));
}
__device__ __forceinline__ int swz(int r, int c){
    return r * 64 + ((((c >> 2) ^ (r & 7))) << 2) + (c & 3);
}

// ---------------- input tf32 rounding ----------------
__global__ void round_k(const float4* __restrict__ in, int which, int n4){
    float4* out = (which == 0) ? (float4*)g_x : (which == 1) ? (float4*)g_wqkv
                                                             : (float4*)g_wout;
    int i = blockIdx.x * blockDim.x + threadIdx.x;
    if (i < n4){
        float4 v = in[i];
        v.x = tf32f(v.x); v.y = tf32f(v.y); v.z = tf32f(v.z); v.w = tf32f(v.w);
        out[i] = v;
    }
}

// ---------------- GEMM: 256x128 tile, tf32 mma, ldmatrix A, padded smem ----
#define SA_W 36                      // A smem row stride (words), 256 rows
#define SB_W 136                     // B smem row stride (words), 32 rows
#define STG_W (256*SA_W + 32*SB_W)   // 13568 words / stage
#define GSMEM_BYTES (3 * STG_W * 4)  // 162816

__global__ __launch_bounds__(256, 1) void gemm_tc(const float* __restrict__ bias,
                                                  float* __restrict__ C, int N, int mode)
{
    extern __shared__ float sm[];
    const float* __restrict__ A = (mode == 0) ? g_x    : g_attn;
    const float* __restrict__ B = (mode == 0) ? g_wqkv : g_wout;

    const int t = threadIdx.x, lane = t & 31, w = t >> 5;
    const int g = lane >> 2, j = lane & 3;
    const int wm = w & 3, wn = w >> 2;           // 4 m-bands x 2 n-bands
    const int m0 = blockIdx.y << 8, n0 = blockIdx.x << 7;

    const int ar = t >> 3, ac4 = t & 7;          // A copy: rows ar+32i (i<8)
    const int bk = t >> 5, bc4 = t & 31;         // B copy: rows bk+8i (i<4)

    // ldmatrix lane geometry
    const int til = lane >> 3, rin = lane & 7;
    const int lrow = (til & 1) * 8 + rin;        // 0..15
    const int lc4o = til >> 1;                   // 0/1
    const unsigned smu = (unsigned)__cvta_generic_to_shared(sm);

    unsigned abase[4];
    #pragma unroll
    for (int mt = 0; mt < 4; mt++)
        abase[mt] = (unsigned)((wm * 64 + mt * 16 + lrow) * SA_W * 4 + lc4o * 16);

    float4 acc[4][8];
    #pragma unroll
    for (int i = 0; i < 4; i++)
        #pragma unroll
        for (int n = 0; n < 8; n++) acc[i][n] = make_float4(0.f, 0.f, 0.f, 0.f);

    auto issue = [&](int kt, int slot){
        float* dA = sm + slot * STG_W;
        const float* sA = A + (size_t)(m0 + ar) * KDIM + kt * 32 + ac4 * 4;
        #pragma unroll
        for (int i = 0; i < 8; i++)
            cpasync16(dA + (ar + 32 * i) * SA_W + ac4 * 4, sA + (size_t)32 * i * KDIM);
        float* dB = sm + slot * STG_W + 256 * SA_W;
        const float* sB = B + (size_t)(kt * 32 + bk) * N + n0 + bc4 * 4;
        #pragma unroll
        for (int i = 0; i < 4; i++)
            cpasync16(dB + (bk + 8 * i) * SB_W + bc4 * 4, sB + (size_t)8 * i * N);
    };

    issue(0, 0); cp_commit();
    issue(1, 1); cp_commit();
    cp_wait<1>();

    for (int kt = 0; kt < 32; kt++){
        __syncthreads();
        if (kt + 2 < 32){ issue(kt + 2, (kt + 2) % 3); cp_commit(); }

        const unsigned as0 = smu + (kt % 3) * STG_W * 4;
        const float* Bb = sm + (kt % 3) * STG_W + 256 * SA_W;
        #pragma unroll
        for (int ks = 0; ks < 4; ks++){
            const int kk = ks * 8;
            unsigned a[4][4];
            #pragma unroll
            for (int mt = 0; mt < 4; mt++) ldsm4(a[mt], as0 + abase[mt] + ks * 32);
            unsigned b0[8], b1[8];
            #pragma unroll
            for (int nt = 0; nt < 8; nt++){
                int nn = wn * 64 + nt * 8 + g;
                b0[nt] = __float_as_uint(Bb[(kk + j) * SB_W + nn]);
                b1[nt] = __float_as_uint(Bb[(kk + j + 4) * SB_W + nn]);
            }
            #pragma unroll
            for (int mt = 0; mt < 4; mt++)
                #pragma unroll
                for (int nt = 0; nt < 8; nt++)
                    mma8(acc[mt][nt], a[mt][0], a[mt][1], a[mt][2], a[mt][3],
                         b0[nt], b1[nt]);
        }
        if (kt + 2 < 32)      cp_wait<1>();
        else if (kt + 1 < 32) cp_wait<0>();
    }

    #pragma unroll
    for (int mt = 0; mt < 4; mt++){
        const int r = m0 + wm * 64 + mt * 16 + g;
        #pragma unroll
        for (int nt = 0; nt < 8; nt++){
            const int f = n0 + wn * 64 + nt * 8 + (j << 1);
            float2 bb = *(const float2*)&bias[f];
            float4 a = acc[mt][nt];
            if (mode == 0){
                int qk = f >> 10, h = (f >> 6) & 15, dd = f & 63;
                float* dst = (qk == 0) ? g_q : (qk == 1) ? g_k : g_v;
                int b_i = r >> 11, pos = r & 2047;
                size_t base = ((size_t)((b_i * NH + h) * SEQ + pos)) * DH + dd;
                *(float2*)&dst[base] =
                    make_float2(tf32f(a.x + bb.x), tf32f(a.y + bb.y));
                *(float2*)&dst[base + 8 * DH] =
                    make_float2(tf32f(a.z + bb.x), tf32f(a.w + bb.y));
            } else {
                size_t off = (size_t)r * DM + f;
                *(float2*)&C[off]          = make_float2(a.x + bb.x, a.y + bb.y);
                *(float2*)&C[off + 8 * DM] = make_float2(a.z + bb.x, a.w + bb.y);
            }
        }
    }
}

// ---------------- causal attention (R4 core + ldmatrix for Q/K/P) ----------
#define AT_SMEM_BYTES ((32768 + 256) * 4)
__global__ __launch_bounds__(256) void attn_tc()
{
    extern __shared__ float sm[];
    float* Ks = sm;                 // 3 x 64x64 (xor-swizzled)
    float* Vs = sm + 12288;         // 3 x 64x64
    float* Ps = sm + 24576;         // 64..: Q staging then P
    float* Ls = sm + 32768;
    const unsigned smu = (unsigned)__cvta_generic_to_shared(sm);
    const unsigned PSB = 24576u * 4u;

    const int qt = gridDim.x - 1 - blockIdx.x;
    const int bh = blockIdx.y;
    const int t = threadIdx.x, lane = t & 31, w = t >> 5;
    const int g = lane >> 2, j = lane & 3;
    const int wm = w & 3, wh = w >> 2;

    const int til = lane >> 3, rin = lane & 7;
    const int lrow = (til & 1) * 8 + rin;
    const int lc4o = til >> 1;

    const float* qg = g_q + ((size_t)bh * SEQ + qt * 128) * DH;
    const float* kg = g_k + (size_t)bh * SEQ * DH;
    const float* vg = g_v + (size_t)bh * SEQ * DH;

    const int lr = t >> 4, lc4 = t & 15;
    auto issueKV = [&](int kt, int slot){
        const float* ksrc = kg + (size_t)kt * 64 * DH;
        const float* vsrc = vg + (size_t)kt * 64 * DH;
        float* kd = Ks + slot * 4096;
        float* vd = Vs + slot * 4096;
        #pragma unroll
        for (int i = 0; i < 4; i++){
            int r = lr + 16 * i;
            int off = swz(r, lc4 * 4);
            cpasync16(kd + off, ksrc + r * 64 + lc4 * 4);
            cpasync16(vd + off, vsrc + r * 64 + lc4 * 4);
        }
    };

    #pragma unroll
    for (int i = 0; i < 8; i++){
        int r = lr + 16 * i;
        cpasync16(Ps + swz(r, lc4 * 4), qg + (size_t)r * 64 + lc4 * 4);
    }
    cp_commit();
    issueKV(0, 0); cp_commit();
    issueKV(1, 1); cp_commit();
    cp_wait<2>();
    __syncthreads();

    // Q fragments via ldmatrix (xor layout: chunk = c4 ^ (row&7), row&7 == rin)
    unsigned qa[2][8][4];
    #pragma unroll
    for (int mt = 0; mt < 2; mt++){
        unsigned rb = PSB + (unsigned)(wm * 32 + mt * 16 + lrow) * 256u;
        #pragma unroll
        for (int ks = 0; ks < 8; ks++){
            unsigned c4 = (unsigned)((ks * 2 + lc4o) ^ rin) << 4;
            ldsm4(qa[mt][ks], smu + rb + c4);
        }
    }
    __syncthreads();
    cp_wait<1>();

    float4 oacc[2][4];
    #pragma unroll
    for (int mt = 0; mt < 2; mt++)
        #pragma unroll
        for (int nt = 0; nt < 4; nt++) oacc[mt][nt] = make_float4(0.f,0.f,0.f,0.f);
    float lpart[2][2] = {{0.f,0.f},{0.f,0.f}};

    const unsigned krb0 = (unsigned)(wh * 32 + lrow) * 256u;
    const int ktmax = 2 * qt + 1;
    for (int kt = 0; kt <= ktmax; kt++){
        __syncthreads();
        if (kt + 2 <= ktmax){ issueKV(kt + 2, (kt + 2) % 3); cp_commit(); }
        const unsigned kbB = smu + (unsigned)((kt % 3) * 16384);
        const float* Vb = Vs + (kt % 3) * 4096;

        float4 sacc[2][4];
        #pragma unroll
        for (int mt = 0; mt < 2; mt++)
            #pragma unroll
            for (int nt = 0; nt < 4; nt++) sacc[mt][nt] = make_float4(0.f,0.f,0.f,0.f);

        #pragma unroll
        for (int ks = 0; ks < 8; ks++){
            unsigned c4 = (unsigned)((ks * 2 + lc4o) ^ rin) << 4;
            unsigned kb[2][4];
            ldsm4(kb[0], kbB + krb0 + c4);            // key rows wh*32+0..15
            ldsm4(kb[1], kbB + krb0 + 4096u + c4);    // key rows wh*32+16..31
            // kb[p] = {b0[2p], b0[2p+1], b1[2p], b1[2p+1]}
            #pragma unroll
            for (int mt = 0; mt < 2; mt++){
                mma8(sacc[mt][0], qa[mt][ks][0], qa[mt][ks][1], qa[mt][ks][2], qa[mt][ks][3], kb[0][0], kb[0][2]);
                mma8(sacc[mt][1], qa[mt][ks][0], qa[mt][ks][1], qa[mt][ks][2], qa[mt][ks][3], kb[0][1], kb[0][3]);
                mma8(sacc[mt][2], qa[mt][ks][0], qa[mt][ks][1], qa[mt][ks][2], qa[mt][ks][3], kb[1][0], kb[1][2]);
                mma8(sacc[mt][3], qa[mt][ks][0], qa[mt][ks][1], qa[mt][ks][2], qa[mt][ks][3], kb[1][1], kb[1][3]);
            }
        }

        const bool diag = (kt >= 2 * qt);
        #pragma unroll
        for (int mt = 0; mt < 2; mt++){
            int r0 = wm * 32 + mt * 16 + g;
            int rq0 = qt * 128 + r0;
            #pragma unroll
            for (int nt = 0; nt < 4; nt++){
                int c  = wh * 32 + nt * 8 + (j << 1);
                int ck = kt * 64 + c;
                float4 s = sacc[mt][nt];
                s.x *= 0.125f; s.y *= 0.125f; s.z *= 0.125f; s.w *= 0.125f;
                if (diag){
                    if (ck     > rq0)     s.x = -CUDART_INF_F;
                    if (ck + 1 > rq0)     s.y = -CUDART_INF_F;
                    if (ck     > rq0 + 8) s.z = -CUDART_INF_F;
                    if (ck + 1 > rq0 + 8) s.w = -CUDART_INF_F;
                }
                float px = tf32f(__expf(s.x));
                float py = tf32f(__expf(s.y));
                float pz = tf32f(__expf(s.z));
                float pw = tf32f(__expf(s.w));
                lpart[mt][0] += px + py;
                lpart[mt][1] += pz + pw;
                *(float2*)&Ps[swz(r0,     c)] = make_float2(px, py);
                *(float2*)&Ps[swz(r0 + 8, c)] = make_float2(pz, pw);
            }
        }
        __syncthreads();

        #pragma unroll
        for (int ks = 0; ks < 8; ks++){
            int kk = ks * 8;
            unsigned c4 = (unsigned)((ks * 2 + lc4o) ^ rin) << 4;
            unsigned pa[2][4];
            #pragma unroll
            for (int mt = 0; mt < 2; mt++)
                ldsm4(pa[mt], smu + PSB + (unsigned)(wm * 32 + mt * 16 + lrow) * 256u + c4);
            unsigned vb0[4], vb1[4];
            #pragma unroll
            for (int nt = 0; nt < 4; nt++){
                int nc = wh * 32 + nt * 8 + g;
                vb0[nt] = __float_as_uint(Vb[swz(kk + j,     nc)]);
                vb1[nt] = __float_as_uint(Vb[swz(kk + j + 4, nc)]);
            }
            #pragma unroll
            for (int mt = 0; mt < 2; mt++)
                #pragma unroll
                for (int nt = 0; nt < 4; nt++)
                    mma8(oacc[mt][nt], pa[mt][0], pa[mt][1], pa[mt][2], pa[mt][3],
                         vb0[nt], vb1[nt]);
        }
        if (kt + 2 <= ktmax)      cp_wait<1>();
        else if (kt + 1 <= ktmax) cp_wait<0>();
    }

    #pragma unroll
    for (int mt = 0; mt < 2; mt++)
        #pragma unroll
        for (int h2 = 0; h2 < 2; h2++){
            float v = lpart[mt][h2];
            v += __shfl_xor_sync(0xffffffffu, v, 1);
            v += __shfl_xor_sync(0xffffffffu, v, 2);
            if (j == 0) Ls[wh * 128 + wm * 32 + mt * 16 + h2 * 8 + g] = v;
        }
    __syncthreads();
    {
        const int b = bh >> 4, h = bh & 15;
        float* od = g_attn + ((size_t)(b * SEQ + qt * 128)) * DM + h * 64;
        #pragma unroll
        for (int mt = 0; mt < 2; mt++){
            int r0 = wm * 32 + mt * 16 + g;
            float i0 = 1.f / (Ls[r0] + Ls[128 + r0]);
            float i1 = 1.f / (Ls[r0 + 8] + Ls[128 + r0 + 8]);
            #pragma unroll
            for (int nt = 0; nt < 4; nt++){
                int c = wh * 32 + nt * 8 + (j << 1);
                float4 a = oacc[mt][nt];
                *(float2*)&od[(size_t)r0 * DM + c] =
                    make_float2(tf32f(a.x * i0), tf32f(a.y * i0));
                *(float2*)&od[(size_t)(r0 + 8) * DM + c] =
                    make_float2(tf32f(a.z * i1), tf32f(a.w * i1));
            }
        }
    }
}

// ---------------------------------------------------------------------------
extern "C" void kernel_launch(void* const* d_in, const int* in_sizes, int n_in,
                              void* d_out, int out_size)
{
    const float* x     = (const float*)d_in[0];
    const float* w_qkv = (const float*)d_in[1];
    const float* b_qkv = (const float*)d_in[2];
    const float* w_out = (const float*)d_in[3];
    const float* b_out = (const float*)d_in[4];
    float* out = (float*)d_out;

    cudaFuncSetAttribute(gemm_tc, cudaFuncAttributeMaxDynamicSharedMemorySize, GSMEM_BYTES);
    cudaFuncSetAttribute(attn_tc, cudaFuncAttributeMaxDynamicSharedMemorySize, AT_SMEM_BYTES);

    round_k<<<(MR * DM / 4 + 255) / 256, 256>>>((const float4*)x,     0, MR * DM / 4);
    round_k<<<(DM * 3 * DM / 4 + 255) / 256, 256>>>((const float4*)w_qkv, 1, DM * 3 * DM / 4);
    round_k<<<(DM * DM / 4 + 255) / 256, 256>>>((const float4*)w_out, 2, DM * DM / 4);

    gemm_tc<<<dim3(24, 32), 256, GSMEM_BYTES>>>(b_qkv, nullptr, 3 * DM, 0);
    attn_tc<<<dim3(SEQ / 128, BH), 256, AT_SMEM_BYTES>>>();
    gemm_tc<<<dim3(8, 32), 256, GSMEM_BYTES>>>(b_out, out, DM, 1);
}

// round 8
// speedup vs baseline: 1.1095x; 1.1095x over previous
#include <cuda_runtime.h>
#include <math_constants.h>

#define SEQ    2048
#define DM     1024
#define NH     16
#define DH     64
#define BH     64
#define MR     8192
#define KDIM   1024

__device__ float g_q[(size_t)BH*SEQ*DH];
__device__ float g_k[(size_t)BH*SEQ*DH];
__device__ float g_v[(size_t)BH*DH*SEQ];     // TRANSPOSED: [bh][d][pos]
__device__ float g_attn[(size_t)MR*DM];
__device__ float g_x[(size_t)MR*DM];
__device__ float g_wqkv[(size_t)3*DM*DM];    // TRANSPOSED: [n][k]
__device__ float g_wout[(size_t)DM*DM];      // TRANSPOSED: [n][k]

__device__ __forceinline__ unsigned cvt_tf32(float f){
    unsigned u; asm("cvt.rna.tf32.f32 %0, %1;" : "=r"(u) : "f"(f)); return u;
}
__device__ __forceinline__ float tf32f(float f){ return __uint_as_float(cvt_tf32(f)); }

__device__ __forceinline__ void mma8(float4& d, unsigned a0, unsigned a1, unsigned a2,
                                     unsigned a3, unsigned b0, unsigned b1){
    asm volatile(
      "mma.sync.aligned.m16n8k8.row.col.f32.tf32.tf32.f32 "
      "{%0,%1,%2,%3},{%4,%5,%6,%7},{%8,%9},{%0,%1,%2,%3};"
      : "+f"(d.x), "+f"(d.y), "+f"(d.z), "+f"(d.w)
      : "r"(a0), "r"(a1), "r"(a2), "r"(a3), "r"(b0), "r"(b1));
}
__device__ __forceinline__ void ldsm4(unsigned* r, unsigned addr){
    asm volatile("ldmatrix.sync.aligned.m8n8.x4.shared.b16 {%0,%1,%2,%3}, [%4];"
        : "=r"(r[0]), "=r"(r[1]), "=r"(r[2]), "=r"(r[3]) : "r"(addr));
}
__device__ __forceinline__ void cpasync16(void* smem, const void* g){
    unsigned s = (unsigned)__cvta_generic_to_shared(smem);
    asm volatile("cp.async.cg.shared.global [%0], [%1], 16;" :: "r"(s), "l"(g));
}
__device__ __forceinline__ void cp_commit(){ asm volatile("cp.async.commit_group;"); }
template<int N> __device__ __forceinline__ void cp_wait(){
    asm volatile("cp.async.wait_group %0;" :: "n"(N));
}
// xor swizzle, 64-word rows (attention tiles)
__device__ __forceinline__ int swz(int r, int c){
    return r * 64 + ((((c >> 2) ^ (r & 7))) << 2) + (c & 3);
}

// ---------------- input passes ----------------
__global__ void round_x(const float4* __restrict__ in, int n4){
    int i = blockIdx.x * blockDim.x + threadIdx.x;
    if (i < n4){
        float4 v = in[i];
        v.x = tf32f(v.x); v.y = tf32f(v.y); v.z = tf32f(v.z); v.w = tf32f(v.w);
        ((float4*)g_x)[i] = v;
    }
}
// in[K][N] row-major -> out[N][K] (tf32-rounded)
__global__ void transpose_w(const float* __restrict__ in, int which, int N){
    __shared__ float tile[32][33];
    float* out = which ? g_wout : g_wqkv;
    int n0 = blockIdx.x * 32, k0 = blockIdx.y * 32;
    int tx = threadIdx.x, ty = threadIdx.y;
    #pragma unroll
    for (int i = 0; i < 32; i += 8)
        tile[ty + i][tx] = in[(size_t)(k0 + ty + i) * N + n0 + tx];
    __syncthreads();
    #pragma unroll
    for (int i = 0; i < 32; i += 8)
        out[(size_t)(n0 + ty + i) * KDIM + k0 + tx] = tf32f(tile[tx][ty + i]);
}

// ---------------- GEMM: 128x128x32, both operands via ldmatrix -------------
// A row-major [M][K]; B pre-transposed [N][K]. Identical tile loaders.
#define GSTG 8192                       // words per stage (A 4096 + B 4096)
#define GSMEM_BYTES (3 * GSTG * 4)      // 98304

__global__ __launch_bounds__(256, 2) void gemm_tc(const float* __restrict__ bias,
                                                  float* __restrict__ C, int mode)
{
    extern __shared__ float sm[];
    const float* __restrict__ A = (mode == 0) ? g_x    : g_attn;
    const float* __restrict__ B = (mode == 0) ? g_wqkv : g_wout;

    const int t = threadIdx.x, lane = t & 31, w = t >> 5;
    const int g = lane >> 2, j = lane & 3;
    const int wm = w >> 2, wn = w & 3;            // 2 m-bands(64) x 4 n-bands(32)
    const int m0 = blockIdx.y << 7, n0 = blockIdx.x << 7;

    const int til = lane >> 3, rin = lane & 7;
    const int lrow = (til & 1) * 8 + rin;
    const int lc4o = til >> 1;
    const unsigned smu = (unsigned)__cvta_generic_to_shared(sm);

    float4 acc[4][4];
    #pragma unroll
    for (int i = 0; i < 4; i++)
        #pragma unroll
        for (int n = 0; n < 4; n++) acc[i][n] = make_float4(0.f, 0.f, 0.f, 0.f);

    const int ldr = t >> 3, ldc = t & 7;          // tile loader: rows ldr+32i, granule ldc
    auto issue = [&](int kt, int slot){
        float* dA = sm + slot * GSTG;
        float* dB = dA + 4096;
        const float* sA = A + (size_t)(m0 + ldr) * KDIM + kt * 32 + ldc * 4;
        const float* sB = B + (size_t)(n0 + ldr) * KDIM + kt * 32 + ldc * 4;
        #pragma unroll
        for (int i = 0; i < 4; i++){
            int rr = ldr + 32 * i;
            int off = rr * 32 + ((ldc ^ (rr & 7)) << 2);
            cpasync16(dA + off, sA + (size_t)32 * i * KDIM);
            cpasync16(dB + off, sB + (size_t)32 * i * KDIM);
        }
    };

    issue(0, 0); cp_commit();
    issue(1, 1); cp_commit();
    cp_wait<1>();

    for (int kt = 0; kt < 32; kt++){
        __syncthreads();
        if (kt + 2 < 32){ issue(kt + 2, (kt + 2) % 3); cp_commit(); }

        const unsigned as0 = smu + (kt % 3) * GSTG * 4;
        const unsigned bs0 = as0 + 4096 * 4;
        #pragma unroll
        for (int ks = 0; ks < 4; ks++){
            const unsigned cof = (unsigned)((ks * 2 + lc4o) ^ rin) << 4;
            unsigned a[4][4];
            #pragma unroll
            for (int mt = 0; mt < 4; mt++)
                ldsm4(a[mt], as0 + (unsigned)(wm * 64 + mt * 16 + lrow) * 128 + cof);
            unsigned bf[2][4];
            #pragma unroll
            for (int np = 0; np < 2; np++)
                ldsm4(bf[np], bs0 + (unsigned)(wn * 32 + np * 16 + lrow) * 128 + cof);
            #pragma unroll
            for (int mt = 0; mt < 4; mt++)
                #pragma unroll
                for (int nt = 0; nt < 4; nt++)
                    mma8(acc[mt][nt], a[mt][0], a[mt][1], a[mt][2], a[mt][3],
                         bf[nt >> 1][nt & 1], bf[nt >> 1][2 + (nt & 1)]);
        }
        if (kt + 2 < 32)      cp_wait<1>();
        else if (kt + 1 < 32) cp_wait<0>();
    }

    #pragma unroll
    for (int mt = 0; mt < 4; mt++){
        const int r = m0 + wm * 64 + mt * 16 + g;
        #pragma unroll
        for (int nt = 0; nt < 4; nt++){
            const int f = n0 + wn * 32 + nt * 8 + (j << 1);
            float2 bb = *(const float2*)&bias[f];
            float4 a = acc[mt][nt];
            if (mode == 0){
                int qk = f >> 10, h = (f >> 6) & 15, dd = f & 63;
                int b_i = r >> 11, pos = r & 2047;
                int bhh = b_i * NH + h;
                if (qk == 2){       // V: transposed store [bh][d][pos]
                    float* vb = g_v + ((size_t)bhh * DH + dd) * SEQ + pos;
                    vb[0]            = tf32f(a.x + bb.x);
                    vb[SEQ]          = tf32f(a.y + bb.y);
                    vb[8]            = tf32f(a.z + bb.x);
                    vb[SEQ + 8]      = tf32f(a.w + bb.y);
                } else {
                    float* dst = (qk == 0) ? g_q : g_k;
                    size_t base = ((size_t)bhh * SEQ + pos) * DH + dd;
                    *(float2*)&dst[base] =
                        make_float2(tf32f(a.x + bb.x), tf32f(a.y + bb.y));
                    *(float2*)&dst[base + 8 * DH] =
                        make_float2(tf32f(a.z + bb.x), tf32f(a.w + bb.y));
                }
            } else {
                size_t off = (size_t)r * DM + f;
                *(float2*)&C[off]          = make_float2(a.x + bb.x, a.y + bb.y);
                *(float2*)&C[off + 8 * DM] = make_float2(a.z + bb.x, a.w + bb.y);
            }
        }
    }
}

// ---------------- causal attention: all operands via ldmatrix ---------------
#define AT_SMEM_BYTES ((32768 + 256) * 4)
__global__ __launch_bounds__(256) void attn_tc()
{
    extern __shared__ float sm[];
    float* Ks = sm;                 // 3 x 64x64 xor-swizzled  (rows = key)
    float* Vs = sm + 12288;         // 3 x 64x64 xor-swizzled  (rows = d, V^T)
    float* Ps = sm + 24576;         // 128x64: Q staging then P
    float* Ls = sm + 32768;
    const unsigned smu = (unsigned)__cvta_generic_to_shared(sm);
    const unsigned PSB = 24576u * 4u;
    const unsigned VSB = 12288u * 4u;

    const int qt = gridDim.x - 1 - blockIdx.x;
    const int bh = blockIdx.y;
    const int t = threadIdx.x, lane = t & 31, w = t >> 5;
    const int g = lane >> 2, j = lane & 3;
    const int wm = w & 3, wh = w >> 2;

    const int til = lane >> 3, rin = lane & 7;
    const int lrow = (til & 1) * 8 + rin;
    const int lc4o = til >> 1;

    const float* qg = g_q + ((size_t)bh * SEQ + qt * 128) * DH;
    const float* kg = g_k + (size_t)bh * SEQ * DH;
    const float* vg = g_v + (size_t)bh * DH * SEQ;   // [d][pos]

    const int lr = t >> 4, lc4 = t & 15;
    auto issueKV = [&](int kt, int slot){
        const float* ksrc = kg + (size_t)kt * 64 * DH;
        float* kd = Ks + slot * 4096;
        float* vd = Vs + slot * 4096;
        #pragma unroll
        for (int i = 0; i < 4; i++){
            int r = lr + 16 * i;
            int off = r * 64 + ((lc4 ^ (r & 7)) << 2);
            cpasync16(kd + off, ksrc + r * 64 + lc4 * 4);                 // K rows=key
            cpasync16(vd + off, vg + (size_t)r * SEQ + kt * 64 + lc4 * 4); // V rows=d
        }
    };

    #pragma unroll
    for (int i = 0; i < 8; i++){
        int r = lr + 16 * i;
        cpasync16(Ps + swz(r, lc4 * 4), qg + (size_t)r * 64 + lc4 * 4);
    }
    cp_commit();
    issueKV(0, 0); cp_commit();
    issueKV(1, 1); cp_commit();
    cp_wait<2>();
    __syncthreads();

    // Q fragments via ldmatrix
    unsigned qa[2][8][4];
    #pragma unroll
    for (int mt = 0; mt < 2; mt++){
        unsigned rb = PSB + (unsigned)(wm * 32 + mt * 16 + lrow) * 256u;
        #pragma unroll
        for (int ks = 0; ks < 8; ks++){
            unsigned c4 = (unsigned)((ks * 2 + lc4o) ^ rin) << 4;
            ldsm4(qa[mt][ks], smu + rb + c4);
        }
    }
    __syncthreads();
    cp_wait<1>();

    float4 oacc[2][4];
    #pragma unroll
    for (int mt = 0; mt < 2; mt++)
        #pragma unroll
        for (int nt = 0; nt < 4; nt++) oacc[mt][nt] = make_float4(0.f,0.f,0.f,0.f);
    float lpart[2][2] = {{0.f,0.f},{0.f,0.f}};

    const unsigned krb0 = (unsigned)(wh * 32 + lrow) * 256u;
    const int ktmax = 2 * qt + 1;
    for (int kt = 0; kt <= ktmax; kt++){
        __syncthreads();
        if (kt + 2 <= ktmax){ issueKV(kt + 2, (kt + 2) % 3); cp_commit(); }
        const unsigned kbB = smu + (unsigned)((kt % 3) * 16384);
        const unsigned vbB = smu + VSB + (unsigned)((kt % 3) * 16384);

        float4 sacc[2][4];
        #pragma unroll
        for (int mt = 0; mt < 2; mt++)
            #pragma unroll
            for (int nt = 0; nt < 4; nt++) sacc[mt][nt] = make_float4(0.f,0.f,0.f,0.f);

        #pragma unroll
        for (int ks = 0; ks < 8; ks++){
            unsigned c4 = (unsigned)((ks * 2 + lc4o) ^ rin) << 4;
            unsigned kb[2][4];
            ldsm4(kb[0], kbB + krb0 + c4);
            ldsm4(kb[1], kbB + krb0 + 4096u + c4);
            #pragma unroll
            for (int mt = 0; mt < 2; mt++){
                mma8(sacc[mt][0], qa[mt][ks][0], qa[mt][ks][1], qa[mt][ks][2], qa[mt][ks][3], kb[0][0], kb[0][2]);
                mma8(sacc[mt][1], qa[mt][ks][0], qa[mt][ks][1], qa[mt][ks][2], qa[mt][ks][3], kb[0][1], kb[0][3]);
                mma8(sacc[mt][2], qa[mt][ks][0], qa[mt][ks][1], qa[mt][ks][2], qa[mt][ks][3], kb[1][0], kb[1][2]);
                mma8(sacc[mt][3], qa[mt][ks][0], qa[mt][ks][1], qa[mt][ks][2], qa[mt][ks][3], kb[1][1], kb[1][3]);
            }
        }

        const bool diag = (kt >= 2 * qt);
        #pragma unroll
        for (int mt = 0; mt < 2; mt++){
            int r0 = wm * 32 + mt * 16 + g;
            int rq0 = qt * 128 + r0;
            #pragma unroll
            for (int nt = 0; nt < 4; nt++){
                int c  = wh * 32 + nt * 8 + (j << 1);
                int ck = kt * 64 + c;
                float4 s = sacc[mt][nt];
                s.x *= 0.125f; s.y *= 0.125f; s.z *= 0.125f; s.w *= 0.125f;
                if (diag){
                    if (ck     > rq0)     s.x = -CUDART_INF_F;
                    if (ck + 1 > rq0)     s.y = -CUDART_INF_F;
                    if (ck     > rq0 + 8) s.z = -CUDART_INF_F;
                    if (ck + 1 > rq0 + 8) s.w = -CUDART_INF_F;
                }
                float px = tf32f(__expf(s.x));
                float py = tf32f(__expf(s.y));
                float pz = tf32f(__expf(s.z));
                float pw = tf32f(__expf(s.w));
                lpart[mt][0] += px + py;
                lpart[mt][1] += pz + pw;
                *(float2*)&Ps[swz(r0,     c)] = make_float2(px, py);
                *(float2*)&Ps[swz(r0 + 8, c)] = make_float2(pz, pw);
            }
        }
        __syncthreads();

        // O += P V  (P via ldsm; V^T via ldsm, rows = d)
        #pragma unroll
        for (int ks = 0; ks < 8; ks++){
            unsigned c4 = (unsigned)((ks * 2 + lc4o) ^ rin) << 4;
            unsigned pa[2][4];
            #pragma unroll
            for (int mt = 0; mt < 2; mt++)
                ldsm4(pa[mt], smu + PSB + (unsigned)(wm * 32 + mt * 16 + lrow) * 256u + c4);
            unsigned vf[2][4];
            #pragma unroll
            for (int np = 0; np < 2; np++)
                ldsm4(vf[np], vbB + (unsigned)(wh * 32 + np * 16 + lrow) * 256u + c4);
            #pragma unroll
            for (int mt = 0; mt < 2; mt++)
                #pragma unroll
                for (int nt = 0; nt < 4; nt++)
                    mma8(oacc[mt][nt], pa[mt][0], pa[mt][1], pa[mt][2], pa[mt][3],
                         vf[nt >> 1][nt & 1], vf[nt >> 1][2 + (nt & 1)]);
        }
        if (kt + 2 <= ktmax)      cp_wait<1>();
        else if (kt + 1 <= ktmax) cp_wait<0>();
    }

    #pragma unroll
    for (int mt = 0; mt < 2; mt++)
        #pragma unroll
        for (int h2 = 0; h2 < 2; h2++){
            float v = lpart[mt][h2];
            v += __shfl_xor_sync(0xffffffffu, v, 1);
            v += __shfl_xor_sync(0xffffffffu, v, 2);
            if (j == 0) Ls[wh * 128 + wm * 32 + mt * 16 + h2 * 8 + g] = v;
        }
    __syncthreads();
    {
        const int b = bh >> 4, h = bh & 15;
        float* od = g_attn + ((size_t)(b * SEQ + qt * 128)) * DM + h * 64;
        #pragma unroll
        for (int mt = 0; mt < 2; mt++){
            int r0 = wm * 32 + mt * 16 + g;
            float i0 = 1.f / (Ls[r0] + Ls[128 + r0]);
            float i1 = 1.f / (Ls[r0 + 8] + Ls[128 + r0 + 8]);
            #pragma unroll
            for (int nt = 0; nt < 4; nt++){
                int c = wh * 32 + nt * 8 + (j << 1);
                float4 a = oacc[mt][nt];
                *(float2*)&od[(size_t)r0 * DM + c] =
                    make_float2(tf32f(a.x * i0), tf32f(a.y * i0));
                *(float2*)&od[(size_t)(r0 + 8) * DM + c] =
                    make_float2(tf32f(a.z * i1), tf32f(a.w * i1));
            }
        }
    }
}

// ---------------------------------------------------------------------------
extern "C" void kernel_launch(void* const* d_in, const int* in_sizes, int n_in,
                              void* d_out, int out_size)
{
    const float* x     = (const float*)d_in[0];
    const float* w_qkv = (const float*)d_in[1];
    const float* b_qkv = (const float*)d_in[2];
    const float* w_out = (const float*)d_in[3];
    const float* b_out = (const float*)d_in[4];
    float* out = (float*)d_out;

    cudaFuncSetAttribute(gemm_tc, cudaFuncAttributeMaxDynamicSharedMemorySize, GSMEM_BYTES);
    cudaFuncSetAttribute(attn_tc, cudaFuncAttributeMaxDynamicSharedMemorySize, AT_SMEM_BYTES);

    round_x<<<(MR * DM / 4 + 255) / 256, 256>>>((const float4*)x, MR * DM / 4);
    transpose_w<<<dim3(96, 32), dim3(32, 8)>>>(w_qkv, 0, 3 * DM);
    transpose_w<<<dim3(32, 32), dim3(32, 8)>>>(w_out, 1, DM);

    gemm_tc<<<dim3(24, 64), 256, GSMEM_BYTES>>>(b_qkv, nullptr, 0);
    attn_tc<<<dim3(SEQ / 128, BH), 256, AT_SMEM_BYTES>>>();
    gemm_tc<<<dim3(8, 64), 256, GSMEM_BYTES>>>(b_out, out, 1);
}

// round 9
// speedup vs baseline: 1.1505x; 1.0370x over previous
#include <cuda_runtime.h>
#include <math_constants.h>

#define SEQ    2048
#define DM     1024
#define NH     16
#define DH     64
#define BH     64
#define MR     8192
#define KDIM   1024

__device__ float g_q[(size_t)BH*SEQ*DH];
__device__ float g_k[(size_t)BH*SEQ*DH];
__device__ float g_v[(size_t)BH*DH*SEQ];     // TRANSPOSED: [bh][d][pos]
__device__ float g_attn[(size_t)MR*DM];
__device__ float g_x[(size_t)MR*DM];
__device__ float g_wqkv[(size_t)3*DM*DM];    // TRANSPOSED: [n][k]
__device__ float g_wout[(size_t)DM*DM];      // TRANSPOSED: [n][k]

__device__ __forceinline__ unsigned cvt_tf32(float f){
    unsigned u; asm("cvt.rna.tf32.f32 %0, %1;" : "=r"(u) : "f"(f)); return u;
}
__device__ __forceinline__ float tf32f(float f){ return __uint_as_float(cvt_tf32(f)); }

__device__ __forceinline__ void mma8(float4& d, unsigned a0, unsigned a1, unsigned a2,
                                     unsigned a3, unsigned b0, unsigned b1){
    asm volatile(
      "mma.sync.aligned.m16n8k8.row.col.f32.tf32.tf32.f32 "
      "{%0,%1,%2,%3},{%4,%5,%6,%7},{%8,%9},{%0,%1,%2,%3};"
      : "+f"(d.x), "+f"(d.y), "+f"(d.z), "+f"(d.w)
      : "r"(a0), "r"(a1), "r"(a2), "r"(a3), "r"(b0), "r"(b1));
}
__device__ __forceinline__ void ldsm4(unsigned* r, unsigned addr){
    asm volatile("ldmatrix.sync.aligned.m8n8.x4.shared.b16 {%0,%1,%2,%3}, [%4];"
        : "=r"(r[0]), "=r"(r[1]), "=r"(r[2]), "=r"(r[3]) : "r"(addr));
}
__device__ __forceinline__ void cpasync16(void* smem, const void* g){
    unsigned s = (unsigned)__cvta_generic_to_shared(smem);
    asm volatile("cp.async.cg.shared.global [%0], [%1], 16;" :: "r"(s), "l"(g));
}
__device__ __forceinline__ void cp_commit(){ asm volatile("cp.async.commit_group;"); }
template<int N> __device__ __forceinline__ void cp_wait(){
    asm volatile("cp.async.wait_group %0;" :: "n"(N));
}
__device__ __forceinline__ int swz(int r, int c){
    return r * 64 + ((((c >> 2) ^ (r & 7))) << 2) + (c & 3);
}

// ---------------- input passes ----------------
__global__ void round_x(const float4* __restrict__ in, int n4){
    int i = blockIdx.x * blockDim.x + threadIdx.x;
    if (i < n4){
        float4 v = in[i];
        v.x = tf32f(v.x); v.y = tf32f(v.y); v.z = tf32f(v.z); v.w = tf32f(v.w);
        ((float4*)g_x)[i] = v;
    }
}
__global__ void transpose_w(const float* __restrict__ in, int which, int N){
    __shared__ float tile[32][33];
    float* out = which ? g_wout : g_wqkv;
    int n0 = blockIdx.x * 32, k0 = blockIdx.y * 32;
    int tx = threadIdx.x, ty = threadIdx.y;
    #pragma unroll
    for (int i = 0; i < 32; i += 8)
        tile[ty + i][tx] = in[(size_t)(k0 + ty + i) * N + n0 + tx];
    __syncthreads();
    #pragma unroll
    for (int i = 0; i < 32; i += 8)
        out[(size_t)(n0 + ty + i) * KDIM + k0 + tx] = tf32f(tile[tx][ty + i]);
}

// ---------------- GEMM: 128x128x32, both operands via ldmatrix (R8) --------
#define GSTG 8192
#define GSMEM_BYTES (3 * GSTG * 4)

__global__ __launch_bounds__(256, 2) void gemm_tc(const float* __restrict__ bias,
                                                  float* __restrict__ C, int mode)
{
    extern __shared__ float sm[];
    const float* __restrict__ A = (mode == 0) ? g_x    : g_attn;
    const float* __restrict__ B = (mode == 0) ? g_wqkv : g_wout;

    const int t = threadIdx.x, lane = t & 31, w = t >> 5;
    const int g = lane >> 2, j = lane & 3;
    const int wm = w >> 2, wn = w & 3;
    const int m0 = blockIdx.y << 7, n0 = blockIdx.x << 7;

    const int til = lane >> 3, rin = lane & 7;
    const int lrow = (til & 1) * 8 + rin;
    const int lc4o = til >> 1;
    const unsigned smu = (unsigned)__cvta_generic_to_shared(sm);

    float4 acc[4][4];
    #pragma unroll
    for (int i = 0; i < 4; i++)
        #pragma unroll
        for (int n = 0; n < 4; n++) acc[i][n] = make_float4(0.f, 0.f, 0.f, 0.f);

    const int ldr = t >> 3, ldc = t & 7;
    auto issue = [&](int kt, int slot){
        float* dA = sm + slot * GSTG;
        float* dB = dA + 4096;
        const float* sA = A + (size_t)(m0 + ldr) * KDIM + kt * 32 + ldc * 4;
        const float* sB = B + (size_t)(n0 + ldr) * KDIM + kt * 32 + ldc * 4;
        #pragma unroll
        for (int i = 0; i < 4; i++){
            int rr = ldr + 32 * i;
            int off = rr * 32 + ((ldc ^ (rr & 7)) << 2);
            cpasync16(dA + off, sA + (size_t)32 * i * KDIM);
            cpasync16(dB + off, sB + (size_t)32 * i * KDIM);
        }
    };

    issue(0, 0); cp_commit();
    issue(1, 1); cp_commit();
    cp_wait<1>();

    for (int kt = 0; kt < 32; kt++){
        __syncthreads();
        if (kt + 2 < 32){ issue(kt + 2, (kt + 2) % 3); cp_commit(); }

        const unsigned as0 = smu + (kt % 3) * GSTG * 4;
        const unsigned bs0 = as0 + 4096 * 4;
        #pragma unroll
        for (int ks = 0; ks < 4; ks++){
            const unsigned cof = (unsigned)((ks * 2 + lc4o) ^ rin) << 4;
            unsigned a[4][4];
            #pragma unroll
            for (int mt = 0; mt < 4; mt++)
                ldsm4(a[mt], as0 + (unsigned)(wm * 64 + mt * 16 + lrow) * 128 + cof);
            unsigned bf[2][4];
            #pragma unroll
            for (int np = 0; np < 2; np++)
                ldsm4(bf[np], bs0 + (unsigned)(wn * 32 + np * 16 + lrow) * 128 + cof);
            #pragma unroll
            for (int mt = 0; mt < 4; mt++)
                #pragma unroll
                for (int nt = 0; nt < 4; nt++)
                    mma8(acc[mt][nt], a[mt][0], a[mt][1], a[mt][2], a[mt][3],
                         bf[nt >> 1][nt & 1], bf[nt >> 1][2 + (nt & 1)]);
        }
        if (kt + 2 < 32)      cp_wait<1>();
        else if (kt + 1 < 32) cp_wait<0>();
    }

    #pragma unroll
    for (int mt = 0; mt < 4; mt++){
        const int r = m0 + wm * 64 + mt * 16 + g;
        #pragma unroll
        for (int nt = 0; nt < 4; nt++){
            const int f = n0 + wn * 32 + nt * 8 + (j << 1);
            float2 bb = *(const float2*)&bias[f];
            float4 a = acc[mt][nt];
            if (mode == 0){
                int qk = f >> 10, h = (f >> 6) & 15, dd = f & 63;
                int b_i = r >> 11, pos = r & 2047;
                int bhh = b_i * NH + h;
                if (qk == 2){
                    float* vb = g_v + ((size_t)bhh * DH + dd) * SEQ + pos;
                    vb[0]       = tf32f(a.x + bb.x);
                    vb[SEQ]     = tf32f(a.y + bb.y);
                    vb[8]       = tf32f(a.z + bb.x);
                    vb[SEQ + 8] = tf32f(a.w + bb.y);
                } else {
                    float* dst = (qk == 0) ? g_q : g_k;
                    size_t base = ((size_t)bhh * SEQ + pos) * DH + dd;
                    *(float2*)&dst[base] =
                        make_float2(tf32f(a.x + bb.x), tf32f(a.y + bb.y));
                    *(float2*)&dst[base + 8 * DH] =
                        make_float2(tf32f(a.z + bb.x), tf32f(a.w + bb.y));
                }
            } else {
                size_t off = (size_t)r * DM + f;
                *(float2*)&C[off]          = make_float2(a.x + bb.x, a.y + bb.y);
                *(float2*)&C[off + 8 * DM] = make_float2(a.z + bb.x, a.w + bb.y);
            }
        }
    }
}

// ---------------- causal attention: warp = 16-row band x ALL keys -----------
// No P smem (shfl regroup), 1 barrier/iter, 98KB smem -> 2 CTAs/SM.
#define AT_SMEM_BYTES (24576 * 4)
__global__ __launch_bounds__(256, 2) void attn_tc()
{
    extern __shared__ float sm[];
    // slot s: K at s*8192, V at s*8192+4096 (words). Q staged in slot 2.
    const unsigned smu = (unsigned)__cvta_generic_to_shared(sm);

    const int qt = gridDim.x - 1 - blockIdx.x;
    const int bh = blockIdx.y;
    const int t = threadIdx.x, lane = t & 31, w = t >> 5;
    const int g = lane >> 2, j = lane & 3;

    const int til = lane >> 3, rin = lane & 7;
    const int lrow = (til & 1) * 8 + rin;
    const int lc4o = til >> 1;

    const float* qg = g_q + ((size_t)bh * SEQ + qt * 128) * DH;
    const float* kg = g_k + (size_t)bh * SEQ * DH;
    const float* vg = g_v + (size_t)bh * DH * SEQ;

    const int lr = t >> 4, lc4 = t & 15;
    auto issueKV = [&](int kt, int slot){
        const float* ksrc = kg + (size_t)kt * 64 * DH;
        float* kd = sm + slot * 8192;
        float* vd = kd + 4096;
        #pragma unroll
        for (int i = 0; i < 4; i++){
            int r = lr + 16 * i;
            int off = r * 64 + ((lc4 ^ (r & 7)) << 2);
            cpasync16(kd + off, ksrc + r * 64 + lc4 * 4);
            cpasync16(vd + off, vg + (size_t)r * SEQ + kt * 64 + lc4 * 4);
        }
    };

    // Q (128x64) into slot 2 (8192 words)
    {
        float* qd = sm + 2 * 8192;
        #pragma unroll
        for (int i = 0; i < 8; i++){
            int r = lr + 16 * i;
            cpasync16(qd + swz(r, lc4 * 4), qg + (size_t)r * 64 + lc4 * 4);
        }
    }
    cp_commit();
    issueKV(0, 0); cp_commit();
    issueKV(1, 1); cp_commit();
    cp_wait<2>();
    __syncthreads();

    // Q fragments (warp rows w*16..w*16+15)
    unsigned qa[8][4];
    {
        unsigned rb = 2u * 8192u * 4u + (unsigned)(w * 16 + lrow) * 256u;
        #pragma unroll
        for (int ks = 0; ks < 8; ks++){
            unsigned c4 = (unsigned)((ks * 2 + lc4o) ^ rin) << 4;
            ldsm4(qa[ks], smu + rb + c4);
        }
    }
    __syncthreads();
    cp_wait<1>();

    float4 oacc[8];
    #pragma unroll
    for (int i = 0; i < 8; i++) oacc[i] = make_float4(0.f, 0.f, 0.f, 0.f);
    float lp0 = 0.f, lp1 = 0.f;

    const int srcA = (g << 2) + (j >> 1);
    const int srcB = srcA + 2;
    const bool odd = (j & 1);
    const int rq0 = qt * 128 + w * 16 + g;

    const int ktmax = 2 * qt + 1;
    for (int kt = 0; kt <= ktmax; kt++){
        __syncthreads();
        if (kt + 2 <= ktmax){ issueKV(kt + 2, (kt + 2) % 3); cp_commit(); }

        const unsigned kB = smu + (unsigned)((kt % 3) * 8192 * 4);
        const unsigned vB = kB + 4096u * 4u;

        // ---- S = Q K^T over all 64 keys ----
        float4 p[8];
        #pragma unroll
        for (int i = 0; i < 8; i++) p[i] = make_float4(0.f, 0.f, 0.f, 0.f);
        #pragma unroll
        for (int ks = 0; ks < 8; ks++){
            unsigned c4 = (unsigned)((ks * 2 + lc4o) ^ rin) << 4;
            unsigned kb[4][4];
            #pragma unroll
            for (int pp = 0; pp < 4; pp++)
                ldsm4(kb[pp], kB + (unsigned)(pp * 16 + lrow) * 256u + c4);
            #pragma unroll
            for (int pp = 0; pp < 4; pp++){
                mma8(p[2*pp],   qa[ks][0], qa[ks][1], qa[ks][2], qa[ks][3], kb[pp][0], kb[pp][2]);
                mma8(p[2*pp+1], qa[ks][0], qa[ks][1], qa[ks][2], qa[ks][3], kb[pp][1], kb[pp][3]);
            }
        }

        // ---- scale, mask, exp ----
        const bool diag = (kt >= 2 * qt);
        #pragma unroll
        for (int nt = 0; nt < 8; nt++){
            int ck = kt * 64 + nt * 8 + (j << 1);
            float4 s = p[nt];
            s.x *= 0.125f; s.y *= 0.125f; s.z *= 0.125f; s.w *= 0.125f;
            if (diag){
                if (ck     > rq0)     s.x = -CUDART_INF_F;
                if (ck + 1 > rq0)     s.y = -CUDART_INF_F;
                if (ck     > rq0 + 8) s.z = -CUDART_INF_F;
                if (ck + 1 > rq0 + 8) s.w = -CUDART_INF_F;
            }
            s.x = tf32f(__expf(s.x)); s.y = tf32f(__expf(s.y));
            s.z = tf32f(__expf(s.z)); s.w = tf32f(__expf(s.w));
            lp0 += s.x + s.y;
            lp1 += s.z + s.w;
            p[nt] = s;
        }

        // ---- O += P V : shfl-regroup P fragments, V^T via ldsm ----
        #pragma unroll
        for (int nt = 0; nt < 8; nt++){
            float4 v = p[nt];
            float ax = __shfl_sync(0xffffffffu, v.x, srcA);
            float ay = __shfl_sync(0xffffffffu, v.y, srcA);
            float az = __shfl_sync(0xffffffffu, v.z, srcA);
            float aw = __shfl_sync(0xffffffffu, v.w, srcA);
            float bx = __shfl_sync(0xffffffffu, v.x, srcB);
            float by = __shfl_sync(0xffffffffu, v.y, srcB);
            float bz = __shfl_sync(0xffffffffu, v.z, srcB);
            float bw = __shfl_sync(0xffffffffu, v.w, srcB);
            unsigned pa0 = __float_as_uint(odd ? ay : ax);
            unsigned pa1 = __float_as_uint(odd ? aw : az);
            unsigned pa2 = __float_as_uint(odd ? by : bx);
            unsigned pa3 = __float_as_uint(odd ? bw : bz);

            unsigned c4 = (unsigned)((nt * 2 + lc4o) ^ rin) << 4;
            unsigned vf[4][4];
            #pragma unroll
            for (int pp = 0; pp < 4; pp++)
                ldsm4(vf[pp], vB + (unsigned)(pp * 16 + lrow) * 256u + c4);
            #pragma unroll
            for (int pp = 0; pp < 4; pp++){
                mma8(oacc[2*pp],   pa0, pa1, pa2, pa3, vf[pp][0], vf[pp][2]);
                mma8(oacc[2*pp+1], pa0, pa1, pa2, pa3, vf[pp][1], vf[pp][3]);
            }
        }

        if (kt + 2 <= ktmax)      cp_wait<1>();
        else if (kt + 1 <= ktmax) cp_wait<0>();
    }

    // ---- row sums (in-warp), normalize, write ----
    lp0 += __shfl_xor_sync(0xffffffffu, lp0, 1);
    lp0 += __shfl_xor_sync(0xffffffffu, lp0, 2);
    lp1 += __shfl_xor_sync(0xffffffffu, lp1, 1);
    lp1 += __shfl_xor_sync(0xffffffffu, lp1, 2);
    const float i0 = 1.f / lp0, i1 = 1.f / lp1;
    {
        const int b = bh >> 4, h = bh & 15;
        const int r0 = qt * 128 + w * 16 + g;
        float* od = g_attn + (size_t)(b * SEQ + r0) * DM + h * 64;
        #pragma unroll
        for (int nt = 0; nt < 8; nt++){
            int c = nt * 8 + (j << 1);
            float4 a = oacc[nt];
            *(float2*)&od[c] =
                make_float2(tf32f(a.x * i0), tf32f(a.y * i0));
            *(float2*)&od[(size_t)8 * DM + c] =
                make_float2(tf32f(a.z * i1), tf32f(a.w * i1));
        }
    }
}

// ---------------------------------------------------------------------------
extern "C" void kernel_launch(void* const* d_in, const int* in_sizes, int n_in,
                              void* d_out, int out_size)
{
    const float* x     = (const float*)d_in[0];
    const float* w_qkv = (const float*)d_in[1];
    const float* b_qkv = (const float*)d_in[2];
    const float* w_out = (const float*)d_in[3];
    const float* b_out = (const float*)d_in[4];
    float* out = (float*)d_out;

    cudaFuncSetAttribute(gemm_tc, cudaFuncAttributeMaxDynamicSharedMemorySize, GSMEM_BYTES);
    cudaFuncSetAttribute(attn_tc, cudaFuncAttributeMaxDynamicSharedMemorySize, AT_SMEM_BYTES);

    round_x<<<(MR * DM / 4 + 255) / 256, 256>>>((const float4*)x, MR * DM / 4);
    transpose_w<<<dim3(96, 32), dim3(32, 8)>>>(w_qkv, 0, 3 * DM);
    transpose_w<<<dim3(32, 32), dim3(32, 8)>>>(w_out, 1, DM);

    gemm_tc<<<dim3(24, 64), 256, GSMEM_BYTES>>>(b_qkv, nullptr, 0);
    attn_tc<<<dim3(SEQ / 128, BH), 256, AT_SMEM_BYTES>>>();
    gemm_tc<<<dim3(8, 64), 256, GSMEM_BYTES>>>(b_out, out, 1);
}